// round 2
// baseline (speedup 1.0000x reference)
#include <cuda_runtime.h>
#include <math.h>

// ---------------- problem constants ----------------
#define Bq    128
#define Hh    256
#define NN    512     // 2H
#define TKq   400
#define EMBq  128
#define Vq    50000
#define OOVq  10
#define VXq   (Vq + OOVq)

#define F_INF __int_as_float(0x7f800000)

// output segment offsets (flattened tuple order)
#define OFF_FINAL 0LL
#define OFF_H    6401280LL                 // B*(V+OOV)
#define OFF_C    (OFF_H  + (long long)Bq*Hh)
#define OFF_CT   (OFF_C  + (long long)Bq*Hh)
#define OFF_ATTN (OFF_CT + (long long)Bq*NN)
#define OFF_PGEN (OFF_ATTN + (long long)Bq*TKq)
#define OFF_COV  (OFF_PGEN + Bq)

// ---------------- scratch (device globals, no allocation) ----------------
__device__ float g_x[Bq * EMBq];
__device__ float g_h1[Bq * Hh];
__device__ float g_c1[Bq * Hh];
__device__ float g_decfea[Bq * NN];
__device__ float g_scores[Bq * TKq];
__device__ float g_attn[Bq * TKq];
__device__ float g_ct[Bq * NN];
__device__ float g_pgen[Bq];
__device__ float g_out1[Bq * Hh];
__device__ float g_logits[(size_t)Bq * Vq];
__device__ float g_rmax[Bq];
__device__ float g_rsum[Bq];

__device__ __forceinline__ float sigmoidf_(float x) {
    return 1.0f / (1.0f + __expf(-x));
}

__device__ __forceinline__ float warpReduceSum(float v) {
    #pragma unroll
    for (int o = 16; o; o >>= 1) v += __shfl_xor_sync(0xffffffffu, v, o);
    return v;
}
__device__ __forceinline__ float warpReduceMax(float v) {
    #pragma unroll
    for (int o = 16; o; o >>= 1) v = fmaxf(v, __shfl_xor_sync(0xffffffffu, v, o));
    return v;
}

// block reduce (up to 1024 threads), red must have >= 32 floats
__device__ __forceinline__ float blockReduceSum(float v, float* red) {
    int w = threadIdx.x >> 5, l = threadIdx.x & 31;
    int nw = (blockDim.x + 31) >> 5;
    v = warpReduceSum(v);
    if (l == 0) red[w] = v;
    __syncthreads();
    float r = (threadIdx.x < nw) ? red[threadIdx.x] : 0.0f;
    if (w == 0) {
        r = warpReduceSum(r);
        if (l == 0) red[0] = r;
    }
    __syncthreads();
    r = red[0];
    __syncthreads();
    return r;
}
__device__ __forceinline__ float blockReduceMax(float v, float* red) {
    int w = threadIdx.x >> 5, l = threadIdx.x & 31;
    int nw = (blockDim.x + 31) >> 5;
    v = warpReduceMax(v);
    if (l == 0) red[w] = v;
    __syncthreads();
    float r = (threadIdx.x < nw) ? red[threadIdx.x] : -F_INF;
    if (w == 0) {
        r = warpReduceMax(r);
        if (l == 0) red[0] = r;
    }
    __syncthreads();
    r = red[0];
    __syncthreads();
    return r;
}

// ---------------- K1: x = cat(c_t_1, emb[y]) @ Wx^T + bx ----------------
__global__ void k_x(const int* __restrict__ y, const float* __restrict__ ct1,
                    const float* __restrict__ emb, const float* __restrict__ Wx,
                    const float* __restrict__ bx) {
    int b = blockIdx.x;
    int e = threadIdx.x; // 128
    __shared__ float in_s[NN + EMBq];
    int yid = y[b];
    for (int j = threadIdx.x; j < NN; j += blockDim.x) in_s[j] = ct1[b * NN + j];
    for (int j = threadIdx.x; j < EMBq; j += blockDim.x)
        in_s[NN + j] = emb[(size_t)yid * EMBq + j];
    __syncthreads();
    const float* w = Wx + (size_t)e * (NN + EMBq);
    float acc = bx[e];
    #pragma unroll 8
    for (int j = 0; j < NN + EMBq; j++) acc = fmaf(in_s[j], w[j], acc);
    g_x[b * EMBq + e] = acc;
}

// ---------------- K2: LSTM cell ----------------
__global__ void k_lstm(const float* __restrict__ h0, const float* __restrict__ c0,
                       const float* __restrict__ w_ih, const float* __restrict__ b_ih,
                       const float* __restrict__ w_hh, const float* __restrict__ b_hh,
                       float* __restrict__ out, long long out_size) {
    int b = blockIdx.x;
    int h = threadIdx.x; // 256
    __shared__ float xs[EMBq], hs[Hh];
    if (h < EMBq) xs[h] = g_x[b * EMBq + h];
    hs[h] = h0[b * Hh + h];
    __syncthreads();

    float acc[4];
    #pragma unroll
    for (int g = 0; g < 4; g++) {
        int k = g * Hh + h;
        float a = b_ih[k] + b_hh[k];
        const float* wi = w_ih + (size_t)k * EMBq;
        #pragma unroll 8
        for (int e = 0; e < EMBq; e++) a = fmaf(xs[e], wi[e], a);
        const float* wh = w_hh + (size_t)k * Hh;
        #pragma unroll 8
        for (int j = 0; j < Hh; j++) a = fmaf(hs[j], wh[j], a);
        acc[g] = a;
    }
    float i_ = sigmoidf_(acc[0]);
    float f_ = sigmoidf_(acc[1]);
    float gg = tanhf(acc[2]);
    float o_ = sigmoidf_(acc[3]);
    float c1 = f_ * c0[b * Hh + h] + i_ * gg;
    float h1 = o_ * tanhf(c1);
    g_h1[b * Hh + h] = h1;
    g_c1[b * Hh + h] = c1;
    long long ih = OFF_H + b * Hh + h;
    long long ic = OFF_C + b * Hh + h;
    if (ih < out_size) out[ih] = h1;
    if (ic < out_size) out[ic] = c1;
}

// ---------------- K3: dec_fea = s_t_hat @ Wp^T + bp ----------------
__global__ void k_decfea(const float* __restrict__ Wp, const float* __restrict__ bp) {
    int b = blockIdx.x;
    int n = threadIdx.x; // 512
    __shared__ float s[NN];
    s[n] = (n < Hh) ? g_h1[b * Hh + n] : g_c1[b * Hh + (n - Hh)];
    __syncthreads();
    const float* w = Wp + (size_t)n * NN;
    float acc = bp[n];
    #pragma unroll 8
    for (int m = 0; m < NN; m++) acc = fmaf(s[m], w[m], acc);
    g_decfea[b * NN + n] = acc;
}

// ---------------- K4: attention scores (warp per (b,t)) ----------------
__global__ void k_scores(const float* __restrict__ encf, const float* __restrict__ cov,
                         const float* __restrict__ Wc, const float* __restrict__ vw) {
    int gw = (blockIdx.x * blockDim.x + threadIdx.x) >> 5;
    int lane = threadIdx.x & 31;
    if (gw >= Bq * TKq) return;
    int b = gw / TKq;
    float cv = cov[gw];
    const float4* ef = (const float4*)(encf + (size_t)gw * NN);
    const float4* df = (const float4*)(g_decfea + (size_t)b * NN);
    const float4* wc = (const float4*)Wc;
    const float4* vv = (const float4*)vw;
    float acc = 0.0f;
    #pragma unroll
    for (int i = lane; i < NN / 4; i += 32) {
        float4 a = ef[i], d = df[i], w = wc[i], v = vv[i];
        acc += tanhf(a.x + d.x + cv * w.x) * v.x;
        acc += tanhf(a.y + d.y + cv * w.y) * v.y;
        acc += tanhf(a.z + d.z + cv * w.z) * v.z;
        acc += tanhf(a.w + d.w + cv * w.w) * v.w;
    }
    acc = warpReduceSum(acc);
    if (lane == 0) g_scores[gw] = acc;
}

// ---------------- K5: softmax over TK + mask + renorm + coverage ----------------
__global__ void k_attsoft(const float* __restrict__ mask, const float* __restrict__ cov,
                          float* __restrict__ out, long long out_size) {
    int b = blockIdx.x;
    int t = threadIdx.x; // 512 threads, TK=400 active
    __shared__ float red[32];
    float sc = (t < TKq) ? g_scores[b * TKq + t] : -F_INF;
    float mx = blockReduceMax(sc, red);
    float ex = 0.0f;
    if (t < TKq) ex = __expf(sc - mx) * mask[b * TKq + t];
    float sum = blockReduceSum(ex, red);
    if (t < TKq) {
        float a = ex / sum;
        g_attn[b * TKq + t] = a;
        long long ia = OFF_ATTN + b * TKq + t;
        if (ia < out_size) out[ia] = a;
        long long icov = OFF_COV + b * TKq + t;
        if (icov < out_size) out[icov] = cov[b * TKq + t] + a;
    }
}

// ---------------- K6: c_t = attn @ encoder_outputs ----------------
__global__ void k_ct(const float* __restrict__ enc, float* __restrict__ out,
                     long long out_size) {
    int b = blockIdx.x;
    int n = threadIdx.x; // 512
    __shared__ float at[TKq];
    for (int j = threadIdx.x; j < TKq; j += blockDim.x) at[j] = g_attn[b * TKq + j];
    __syncthreads();
    const float* e = enc + (size_t)b * TKq * NN + n;
    float acc = 0.0f;
    #pragma unroll 4
    for (int t = 0; t < TKq; t++) acc = fmaf(at[t], e[(size_t)t * NN], acc);
    g_ct[b * NN + n] = acc;
    long long ic = OFF_CT + b * NN + n;
    if (ic < out_size) out[ic] = acc;
}

// ---------------- K7: p_gen ----------------
__global__ void k_pgen(const float* __restrict__ Wpg, const float* __restrict__ bpg,
                       float* __restrict__ out, long long out_size) {
    int b = blockIdx.x;
    __shared__ float red[32];
    float acc = 0.0f;
    // p_gen_in = [c_t(512), h1(256), c1(256), x(128)]  -> 1152
    for (int j = threadIdx.x; j < 1152; j += blockDim.x) {
        float v;
        if (j < 512)       v = g_ct[b * NN + j];
        else if (j < 768)  v = g_h1[b * Hh + (j - 512)];
        else if (j < 1024) v = g_c1[b * Hh + (j - 768)];
        else               v = g_x[b * EMBq + (j - 1024)];
        acc = fmaf(v, Wpg[j], acc);
    }
    acc = blockReduceSum(acc, red);
    if (threadIdx.x == 0) {
        float p = sigmoidf_(acc + bpg[0]);
        g_pgen[b] = p;
        long long ip = OFF_PGEN + b;
        if (ip < out_size) out[ip] = p;
    }
}

// ---------------- K8: output = cat(h1, c_t) @ W1^T + b1 ----------------
__global__ void k_out1(const float* __restrict__ W1, const float* __restrict__ b1) {
    int b = blockIdx.x;
    int h = threadIdx.x; // 256
    __shared__ float s[Hh + NN]; // 768
    s[h] = g_h1[b * Hh + h];
    s[Hh + h] = g_ct[b * NN + h];
    s[Hh + Hh + h] = g_ct[b * NN + Hh + h];
    __syncthreads();
    const float* w = W1 + (size_t)h * (Hh + NN);
    float acc = b1[h];
    #pragma unroll 8
    for (int j = 0; j < Hh + NN; j++) acc = fmaf(s[j], w[j], acc);
    g_out1[b * Hh + h] = acc;
}

// ---------------- K9: logits GEMM  C[b,v] = out1[b,:] . W2[v,:] + b2[v] ----------------
#define GN 128
#define GK 32
__global__ void k_logits(const float* __restrict__ W2, const float* __restrict__ b2) {
    __shared__ float As[GK][Bq + 1];
    __shared__ float Bs[GK][GN + 1];
    int n0 = blockIdx.x * GN;
    int tid = threadIdx.x;          // 256
    int tx = tid & 15;              // vocab group
    int ty = tid >> 4;              // batch group
    float acc[8][8];
    #pragma unroll
    for (int i = 0; i < 8; i++)
        #pragma unroll
        for (int j = 0; j < 8; j++) acc[i][j] = 0.0f;

    for (int kk = 0; kk < Hh; kk += GK) {
        #pragma unroll
        for (int i = 0; i < 4; i++) {
            int idx = tid + i * 256;       // 0..1023 float4 slots
            int m = idx >> 3;              // row 0..127
            int k4 = (idx & 7) * 4;        // k offset 0..28
            float4 a = *(const float4*)(g_out1 + (size_t)m * Hh + kk + k4);
            As[k4 + 0][m] = a.x; As[k4 + 1][m] = a.y;
            As[k4 + 2][m] = a.z; As[k4 + 3][m] = a.w;
            int n = n0 + m;
            float4 w = make_float4(0.f, 0.f, 0.f, 0.f);
            if (n < Vq) w = *(const float4*)(W2 + (size_t)n * Hh + kk + k4);
            Bs[k4 + 0][m] = w.x; Bs[k4 + 1][m] = w.y;
            Bs[k4 + 2][m] = w.z; Bs[k4 + 3][m] = w.w;
        }
        __syncthreads();
        #pragma unroll
        for (int k = 0; k < GK; k++) {
            float a[8], bb[8];
            #pragma unroll
            for (int i = 0; i < 8; i++) a[i] = As[k][ty + 16 * i];
            #pragma unroll
            for (int j = 0; j < 8; j++) bb[j] = Bs[k][tx + 16 * j];
            #pragma unroll
            for (int i = 0; i < 8; i++)
                #pragma unroll
                for (int j = 0; j < 8; j++) acc[i][j] = fmaf(a[i], bb[j], acc[i][j]);
        }
        __syncthreads();
    }
    #pragma unroll
    for (int i = 0; i < 8; i++) {
        int m = ty + 16 * i;
        #pragma unroll
        for (int j = 0; j < 8; j++) {
            int v = n0 + tx + 16 * j;
            if (v < Vq) g_logits[(size_t)m * Vq + v] = acc[i][j] + b2[v];
        }
    }
}

// ---------------- K10: per-row max & sumexp over V ----------------
__global__ void k_vstats() {
    int b = blockIdx.x;
    __shared__ float red[32];
    const float* row = g_logits + (size_t)b * Vq;
    float m = -F_INF;
    for (int v = threadIdx.x; v < Vq; v += blockDim.x) m = fmaxf(m, row[v]);
    m = blockReduceMax(m, red);
    float s = 0.0f;
    for (int v = threadIdx.x; v < Vq; v += blockDim.x) s += __expf(row[v] - m);
    s = blockReduceSum(s, red);
    if (threadIdx.x == 0) { g_rmax[b] = m; g_rsum[b] = s; }
}

// ---------------- K11: base final dist ----------------
__global__ void k_final(float* __restrict__ out, long long out_size) {
    int v = blockIdx.x * blockDim.x + threadIdx.x;
    int b = blockIdx.y;
    if (v >= VXq) return;
    float val = 0.0f;
    if (v < Vq)
        val = g_pgen[b] * __expf(g_logits[(size_t)b * Vq + v] - g_rmax[b]) / g_rsum[b];
    long long idx = OFF_FINAL + (long long)b * VXq + v;
    if (idx < out_size) out[idx] = val;
}

// ---------------- K12: copy scatter-add ----------------
__global__ void k_scatter(const int* __restrict__ ebev, float* __restrict__ out,
                          long long out_size) {
    int i = blockIdx.x * blockDim.x + threadIdx.x;
    if (i >= Bq * TKq) return;
    int b = i / TKq;
    float add = (1.0f - g_pgen[b]) * g_attn[i];
    int tgt = ebev[i];
    long long idx = OFF_FINAL + (long long)b * VXq + tgt;
    if (idx < out_size && tgt >= 0 && tgt < VXq) atomicAdd(&out[idx], add);
}

// ---------------- launch ----------------
extern "C" void kernel_launch(void* const* d_in, const int* in_sizes, int n_in,
                              void* d_out, int out_size) {
    const int*   y        = (const int*)  d_in[0];
    const float* s_h      = (const float*)d_in[1];
    const float* s_c      = (const float*)d_in[2];
    const float* enc_out  = (const float*)d_in[3];
    const float* enc_feat = (const float*)d_in[4];
    const float* mask     = (const float*)d_in[5];
    const float* ct1      = (const float*)d_in[6];
    const int*   ebev     = (const int*)  d_in[8];
    const float* cov      = (const float*)d_in[9];
    const float* emb      = (const float*)d_in[11];
    const float* Wx       = (const float*)d_in[12];
    const float* bx       = (const float*)d_in[13];
    const float* w_ih     = (const float*)d_in[14];
    const float* b_ih     = (const float*)d_in[15];
    const float* w_hh     = (const float*)d_in[16];
    const float* b_hh     = (const float*)d_in[17];
    const float* Wp       = (const float*)d_in[18];
    const float* bp       = (const float*)d_in[19];
    const float* v_w      = (const float*)d_in[20];
    const float* Wc       = (const float*)d_in[21];
    const float* Wpg      = (const float*)d_in[22];
    const float* bpg      = (const float*)d_in[23];
    const float* W1       = (const float*)d_in[24];
    const float* b1       = (const float*)d_in[25];
    const float* W2       = (const float*)d_in[26];
    const float* b2       = (const float*)d_in[27];
    float* out = (float*)d_out;
    long long osz = (long long)out_size;

    k_x<<<Bq, 128>>>(y, ct1, emb, Wx, bx);
    k_lstm<<<Bq, 256>>>(s_h, s_c, w_ih, b_ih, w_hh, b_hh, out, osz);
    k_decfea<<<Bq, 512>>>(Wp, bp);
    k_scores<<<(Bq * TKq) / 8, 256>>>(enc_feat, cov, Wc, v_w);
    k_attsoft<<<Bq, 512>>>(mask, cov, out, osz);
    k_ct<<<Bq, 512>>>(enc_out, out, osz);
    k_pgen<<<Bq, 128>>>(Wpg, bpg, out, osz);
    k_out1<<<Bq, 256>>>(W1, b1);
    k_logits<<<(Vq + GN - 1) / GN, 256>>>(W2, b2);
    k_vstats<<<Bq, 256>>>();
    dim3 gf((VXq + 511) / 512, Bq);
    k_final<<<gf, 512>>>(out, osz);
    k_scatter<<<(Bq * TKq + 255) / 256, 256>>>(ebev, out, osz);
}

// round 3
// speedup vs baseline: 1.7933x; 1.7933x over previous
#include <cuda_runtime.h>
#include <math.h>

// ---------------- problem constants ----------------
#define Bq    128
#define Hh    256
#define NN    512     // 2H
#define TKq   400
#define EMBq  128
#define Vq    50000
#define OOVq  10
#define VXq   (Vq + OOVq)

#define F_INF __int_as_float(0x7f800000)

// output segment offsets (flattened tuple order)
#define OFF_FINAL 0LL
#define OFF_H    6401280LL                 // B*(V+OOV)
#define OFF_C    (OFF_H  + (long long)Bq*Hh)
#define OFF_CT   (OFF_C  + (long long)Bq*Hh)
#define OFF_ATTN (OFF_CT + (long long)Bq*NN)
#define OFF_PGEN (OFF_ATTN + (long long)Bq*TKq)
#define OFF_COV  (OFF_PGEN + Bq)

// ---------------- scratch (device globals, no allocation) ----------------
__device__ float g_emb[Bq * EMBq];
__device__ float g_x[Bq * EMBq];
__device__ float g_gates[Bq * 4 * Hh];
__device__ float g_h1[Bq * Hh];
__device__ float g_c1[Bq * Hh];
__device__ float g_decfea[Bq * NN];
__device__ float g_scores[Bq * TKq];
__device__ float g_attn[Bq * TKq];
__device__ float g_ct[Bq * NN];
__device__ float g_pgen[Bq];
__device__ float g_out1[Bq * Hh];
__device__ float g_logits[(size_t)Bq * Vq];
__device__ float g_pm[Bq * 4];
__device__ float g_ps[Bq * 4];

__device__ __forceinline__ float sigmoidf_(float x) {
    return 1.0f / (1.0f + __expf(-x));
}
__device__ __forceinline__ float tanh_fast(float x) {
    float y;
    asm("tanh.approx.f32 %0, %1;" : "=f"(y) : "f"(x));
    return y;
}

__device__ __forceinline__ float warpReduceSum(float v) {
    #pragma unroll
    for (int o = 16; o; o >>= 1) v += __shfl_xor_sync(0xffffffffu, v, o);
    return v;
}
__device__ __forceinline__ float warpReduceMax(float v) {
    #pragma unroll
    for (int o = 16; o; o >>= 1) v = fmaxf(v, __shfl_xor_sync(0xffffffffu, v, o));
    return v;
}
__device__ __forceinline__ float blockReduceSum(float v, float* red) {
    int w = threadIdx.x >> 5, l = threadIdx.x & 31;
    int nw = (blockDim.x + 31) >> 5;
    v = warpReduceSum(v);
    if (l == 0) red[w] = v;
    __syncthreads();
    float r = (threadIdx.x < nw) ? red[threadIdx.x] : 0.0f;
    if (w == 0) {
        r = warpReduceSum(r);
        if (l == 0) red[0] = r;
    }
    __syncthreads();
    r = red[0];
    __syncthreads();
    return r;
}
__device__ __forceinline__ float blockReduceMax(float v, float* red) {
    int w = threadIdx.x >> 5, l = threadIdx.x & 31;
    int nw = (blockDim.x + 31) >> 5;
    v = warpReduceMax(v);
    if (l == 0) red[w] = v;
    __syncthreads();
    float r = (threadIdx.x < nw) ? red[threadIdx.x] : -F_INF;
    if (w == 0) {
        r = warpReduceMax(r);
        if (l == 0) red[0] = r;
    }
    __syncthreads();
    r = red[0];
    __syncthreads();
    return r;
}

// ---------------- embedding gather ----------------
__global__ void k_emb(const int* __restrict__ y, const float* __restrict__ emb) {
    int b = blockIdx.x;
    g_emb[b * EMBq + threadIdx.x] = emb[(size_t)y[b] * EMBq + threadIdx.x];
}

// ---------------- generic 2-segment GEMM ----------------
// C[128][N] = A1[128][K1] @ W1[N][K1]^T + A2[128][K2] @ W2[N][K2]^T + bias
// W1/W2 are column-offset views into weight matrices with row strides ws1/ws2.
// Grid: (N/32, 2), block 256. Mtile=64, Ntile=32, Ktile=32.
__global__ __launch_bounds__(256) void gemm_seg(
    const float* __restrict__ A1, int lda1, const float* __restrict__ Wg1, int ws1,
    const float* __restrict__ A2, int lda2, const float* __restrict__ Wg2, int ws2,
    int K1, int K2, const float* __restrict__ bias, float* __restrict__ C, int N) {
    __shared__ float As[32][65];
    __shared__ float Bs[32][33];
    int n0 = blockIdx.x * 32;
    int m0 = blockIdx.y * 64;
    int tid = threadIdx.x;
    int tidn = tid & 15;
    int tidm = tid >> 4;
    float acc[4][2];
    #pragma unroll
    for (int i = 0; i < 4; i++) { acc[i][0] = 0.f; acc[i][1] = 0.f; }

    int K = K1 + K2;
    for (int kk = 0; kk < K; kk += 32) {
        const float* Aseg; const float* Wseg; int lda, ws, ko;
        if (kk < K1) { Aseg = A1; Wseg = Wg1; lda = lda1; ws = ws1; ko = kk; }
        else         { Aseg = A2; Wseg = Wg2; lda = lda2; ws = ws2; ko = kk - K1; }
        // A tile: 64 rows x 32 k = 512 float4, 2 per thread
        #pragma unroll
        for (int it = 0; it < 2; it++) {
            int idx = tid + it * 256;
            int m = idx >> 3;
            int k4 = (idx & 7) * 4;
            float4 a = *(const float4*)(Aseg + (size_t)(m0 + m) * lda + ko + k4);
            As[k4 + 0][m] = a.x; As[k4 + 1][m] = a.y;
            As[k4 + 2][m] = a.z; As[k4 + 3][m] = a.w;
        }
        // W tile: 32 rows x 32 k = 256 float4, 1 per thread
        {
            int n = tid >> 3;
            int k4 = (tid & 7) * 4;
            float4 w = *(const float4*)(Wseg + (size_t)(n0 + n) * ws + ko + k4);
            Bs[k4 + 0][n] = w.x; Bs[k4 + 1][n] = w.y;
            Bs[k4 + 2][n] = w.z; Bs[k4 + 3][n] = w.w;
        }
        __syncthreads();
        #pragma unroll
        for (int k = 0; k < 32; k++) {
            float a[4], bb[2];
            #pragma unroll
            for (int i = 0; i < 4; i++) a[i] = As[k][tidm + 16 * i];
            bb[0] = Bs[k][tidn];
            bb[1] = Bs[k][tidn + 16];
            #pragma unroll
            for (int i = 0; i < 4; i++) {
                acc[i][0] = fmaf(a[i], bb[0], acc[i][0]);
                acc[i][1] = fmaf(a[i], bb[1], acc[i][1]);
            }
        }
        __syncthreads();
    }
    #pragma unroll
    for (int j = 0; j < 2; j++) {
        int n = n0 + tidn + 16 * j;
        float bv = bias ? bias[n] : 0.0f;
        #pragma unroll
        for (int i = 0; i < 4; i++) {
            int m = m0 + tidm + 16 * i;
            C[(size_t)m * N + n] = acc[i][j] + bv;
        }
    }
}

// ---------------- LSTM elementwise ----------------
__global__ void k_lstm_elem(const float* __restrict__ c0,
                            const float* __restrict__ b_ih, const float* __restrict__ b_hh,
                            float* __restrict__ out, long long out_size) {
    int b = blockIdx.x;
    int h = threadIdx.x; // 256
    const float* g = g_gates + (size_t)b * 4 * Hh;
    float gi = g[h]            + b_ih[h]            + b_hh[h];
    float gf = g[Hh + h]       + b_ih[Hh + h]       + b_hh[Hh + h];
    float gg = g[2 * Hh + h]   + b_ih[2 * Hh + h]   + b_hh[2 * Hh + h];
    float go = g[3 * Hh + h]   + b_ih[3 * Hh + h]   + b_hh[3 * Hh + h];
    float c1 = sigmoidf_(gf) * c0[b * Hh + h] + sigmoidf_(gi) * tanhf(gg);
    float h1 = sigmoidf_(go) * tanhf(c1);
    g_h1[b * Hh + h] = h1;
    g_c1[b * Hh + h] = c1;
    long long ih = OFF_H + b * Hh + h;
    long long ic = OFF_C + b * Hh + h;
    if (ih < out_size) out[ih] = h1;
    if (ic < out_size) out[ic] = c1;
}

// ---------------- attention scores (warp per (b,t)) ----------------
__global__ void k_scores(const float* __restrict__ encf, const float* __restrict__ cov,
                         const float* __restrict__ Wc, const float* __restrict__ vw) {
    int gw = (blockIdx.x * blockDim.x + threadIdx.x) >> 5;
    int lane = threadIdx.x & 31;
    if (gw >= Bq * TKq) return;
    int b = gw / TKq;
    float cv = cov[gw];
    const float4* ef = (const float4*)(encf + (size_t)gw * NN);
    const float4* df = (const float4*)(g_decfea + (size_t)b * NN);
    const float4* wc = (const float4*)Wc;
    const float4* vv = (const float4*)vw;
    float acc = 0.0f;
    #pragma unroll
    for (int i = lane; i < NN / 4; i += 32) {
        float4 a = ef[i], d = df[i], w = wc[i], v = vv[i];
        acc += tanh_fast(a.x + d.x + cv * w.x) * v.x;
        acc += tanh_fast(a.y + d.y + cv * w.y) * v.y;
        acc += tanh_fast(a.z + d.z + cv * w.z) * v.z;
        acc += tanh_fast(a.w + d.w + cv * w.w) * v.w;
    }
    acc = warpReduceSum(acc);
    if (lane == 0) g_scores[gw] = acc;
}

// ---------------- attention softmax + coverage ----------------
__global__ void k_attsoft(const float* __restrict__ mask, const float* __restrict__ cov,
                          float* __restrict__ out, long long out_size) {
    int b = blockIdx.x;
    int t = threadIdx.x; // 512 threads, TK=400 active
    __shared__ float red[32];
    float sc = (t < TKq) ? g_scores[b * TKq + t] : -F_INF;
    float mx = blockReduceMax(sc, red);
    float ex = 0.0f;
    if (t < TKq) ex = __expf(sc - mx) * mask[b * TKq + t];
    float sum = blockReduceSum(ex, red);
    if (t < TKq) {
        float a = ex / sum;
        g_attn[b * TKq + t] = a;
        long long ia = OFF_ATTN + b * TKq + t;
        if (ia < out_size) out[ia] = a;
        long long icov = OFF_COV + b * TKq + t;
        if (icov < out_size) out[icov] = cov[b * TKq + t] + a;
    }
}

// ---------------- c_t = attn @ encoder_outputs ----------------
__global__ void k_ct(const float* __restrict__ enc, float* __restrict__ out,
                     long long out_size) {
    int b = blockIdx.x;
    int n = threadIdx.x; // 512
    __shared__ float at[TKq];
    for (int j = threadIdx.x; j < TKq; j += blockDim.x) at[j] = g_attn[b * TKq + j];
    __syncthreads();
    const float* e = enc + (size_t)b * TKq * NN + n;
    float acc = 0.0f;
    #pragma unroll 4
    for (int t = 0; t < TKq; t++) acc = fmaf(at[t], e[(size_t)t * NN], acc);
    g_ct[b * NN + n] = acc;
    long long ic = OFF_CT + b * NN + n;
    if (ic < out_size) out[ic] = acc;
}

// ---------------- p_gen ----------------
__global__ void k_pgen(const float* __restrict__ Wpg, const float* __restrict__ bpg,
                       float* __restrict__ out, long long out_size) {
    int b = blockIdx.x;
    __shared__ float red[32];
    float acc = 0.0f;
    for (int j = threadIdx.x; j < 1152; j += blockDim.x) {
        float v;
        if (j < 512)       v = g_ct[b * NN + j];
        else if (j < 768)  v = g_h1[b * Hh + (j - 512)];
        else if (j < 1024) v = g_c1[b * Hh + (j - 768)];
        else               v = g_x[b * EMBq + (j - 1024)];
        acc = fmaf(v, Wpg[j], acc);
    }
    acc = blockReduceSum(acc, red);
    if (threadIdx.x == 0) {
        float p = sigmoidf_(acc + bpg[0]);
        g_pgen[b] = p;
        long long ip = OFF_PGEN + b;
        if (ip < out_size) out[ip] = p;
    }
}

// ---------------- logits GEMM ----------------
#define GN 128
#define GK 32
__global__ __launch_bounds__(256, 2) void k_logits(const float* __restrict__ W2,
                                                   const float* __restrict__ b2) {
    __shared__ float As[GK][Bq + 1];
    __shared__ float Bs[GK][GN + 1];
    int n0 = blockIdx.x * GN;
    int tid = threadIdx.x;
    int tx = tid & 15;
    int ty = tid >> 4;
    float acc[8][8];
    #pragma unroll
    for (int i = 0; i < 8; i++)
        #pragma unroll
        for (int j = 0; j < 8; j++) acc[i][j] = 0.0f;

    for (int kk = 0; kk < Hh; kk += GK) {
        #pragma unroll
        for (int i = 0; i < 4; i++) {
            int idx = tid + i * 256;
            int m = idx >> 3;
            int k4 = (idx & 7) * 4;
            float4 a = *(const float4*)(g_out1 + (size_t)m * Hh + kk + k4);
            As[k4 + 0][m] = a.x; As[k4 + 1][m] = a.y;
            As[k4 + 2][m] = a.z; As[k4 + 3][m] = a.w;
            int n = n0 + m;
            float4 w = make_float4(0.f, 0.f, 0.f, 0.f);
            if (n < Vq) w = *(const float4*)(W2 + (size_t)n * Hh + kk + k4);
            Bs[k4 + 0][m] = w.x; Bs[k4 + 1][m] = w.y;
            Bs[k4 + 2][m] = w.z; Bs[k4 + 3][m] = w.w;
        }
        __syncthreads();
        #pragma unroll
        for (int k = 0; k < GK; k++) {
            float a[8], bb[8];
            #pragma unroll
            for (int i = 0; i < 8; i++) a[i] = As[k][ty + 16 * i];
            #pragma unroll
            for (int j = 0; j < 8; j++) bb[j] = Bs[k][tx + 16 * j];
            #pragma unroll
            for (int i = 0; i < 8; i++)
                #pragma unroll
                for (int j = 0; j < 8; j++) acc[i][j] = fmaf(a[i], bb[j], acc[i][j]);
        }
        __syncthreads();
    }
    #pragma unroll
    for (int i = 0; i < 8; i++) {
        int m = ty + 16 * i;
        #pragma unroll
        for (int j = 0; j < 8; j++) {
            int v = n0 + tx + 16 * j;
            if (v < Vq) g_logits[(size_t)m * Vq + v] = acc[i][j] + b2[v];
        }
    }
}

// ---------------- vocab softmax stats: online, 4-way split ----------------
__global__ void k_vstats() {
    int b = blockIdx.y;
    int chunk = blockIdx.x; // 0..3
    int v0 = chunk * (Vq / 4);
    int v1 = v0 + (Vq / 4);
    const float* row = g_logits + (size_t)b * Vq;
    float m = -F_INF, s = 0.0f;
    for (int v = v0 + threadIdx.x; v < v1; v += blockDim.x) {
        float x = row[v];
        if (x > m) { s *= __expf(m - x); m = x; }
        s += __expf(x - m);
    }
    // warp merge
    #pragma unroll
    for (int o = 16; o; o >>= 1) {
        float m2 = __shfl_xor_sync(0xffffffffu, m, o);
        float s2 = __shfl_xor_sync(0xffffffffu, s, o);
        float mn = fmaxf(m, m2);
        s = s * __expf(m - mn) + s2 * __expf(m2 - mn);
        m = mn;
    }
    __shared__ float sm[8], ss[8];
    int w = threadIdx.x >> 5, l = threadIdx.x & 31;
    if (l == 0) { sm[w] = m; ss[w] = s; }
    __syncthreads();
    if (threadIdx.x == 0) {
        int nw = blockDim.x >> 5;
        float M = sm[0], S = ss[0];
        for (int i = 1; i < nw; i++) {
            float mn = fmaxf(M, sm[i]);
            S = S * __expf(M - mn) + ss[i] * __expf(sm[i] - mn);
            M = mn;
        }
        g_pm[b * 4 + chunk] = M;
        g_ps[b * 4 + chunk] = S;
    }
}

// ---------------- final dist base ----------------
__global__ void k_final(float* __restrict__ out, long long out_size) {
    int v = blockIdx.x * blockDim.x + threadIdx.x;
    int b = blockIdx.y;
    if (v >= VXq) return;
    float M = g_pm[b * 4], S = g_ps[b * 4];
    #pragma unroll
    for (int i = 1; i < 4; i++) {
        float m2 = g_pm[b * 4 + i], s2 = g_ps[b * 4 + i];
        float mn = fmaxf(M, m2);
        S = S * __expf(M - mn) + s2 * __expf(m2 - mn);
        M = mn;
    }
    float val = 0.0f;
    if (v < Vq)
        val = g_pgen[b] * __expf(g_logits[(size_t)b * Vq + v] - M) / S;
    long long idx = OFF_FINAL + (long long)b * VXq + v;
    if (idx < out_size) out[idx] = val;
}

// ---------------- copy scatter-add ----------------
__global__ void k_scatter(const int* __restrict__ ebev, float* __restrict__ out,
                          long long out_size) {
    int i = blockIdx.x * blockDim.x + threadIdx.x;
    if (i >= Bq * TKq) return;
    int b = i / TKq;
    float add = (1.0f - g_pgen[b]) * g_attn[i];
    int tgt = ebev[i];
    long long idx = OFF_FINAL + (long long)b * VXq + tgt;
    if (idx < out_size && tgt >= 0 && tgt < VXq) atomicAdd(&out[idx], add);
}

// ---------------- launch ----------------
extern "C" void kernel_launch(void* const* d_in, const int* in_sizes, int n_in,
                              void* d_out, int out_size) {
    const int*   y        = (const int*)  d_in[0];
    const float* s_h      = (const float*)d_in[1];
    const float* s_c      = (const float*)d_in[2];
    const float* enc_out  = (const float*)d_in[3];
    const float* enc_feat = (const float*)d_in[4];
    const float* mask     = (const float*)d_in[5];
    const float* ct1      = (const float*)d_in[6];
    const int*   ebev     = (const int*)  d_in[8];
    const float* cov      = (const float*)d_in[9];
    const float* emb      = (const float*)d_in[11];
    const float* Wx       = (const float*)d_in[12];
    const float* bx       = (const float*)d_in[13];
    const float* w_ih     = (const float*)d_in[14];
    const float* b_ih     = (const float*)d_in[15];
    const float* w_hh     = (const float*)d_in[16];
    const float* b_hh     = (const float*)d_in[17];
    const float* Wp       = (const float*)d_in[18];
    const float* bp       = (const float*)d_in[19];
    const float* v_w      = (const float*)d_in[20];
    const float* Wc       = (const float*)d_in[21];
    const float* Wpg      = (const float*)d_in[22];
    const float* bpg      = (const float*)d_in[23];
    const float* W1       = (const float*)d_in[24];
    const float* b1       = (const float*)d_in[25];
    const float* W2       = (const float*)d_in[26];
    const float* b2       = (const float*)d_in[27];
    float* out = (float*)d_out;
    long long osz = (long long)out_size;

    float* pg_emb;    cudaGetSymbolAddress((void**)&pg_emb, g_emb);
    float* pg_x;      cudaGetSymbolAddress((void**)&pg_x, g_x);
    float* pg_gates;  cudaGetSymbolAddress((void**)&pg_gates, g_gates);
    float* pg_h1;     cudaGetSymbolAddress((void**)&pg_h1, g_h1);
    float* pg_c1;     cudaGetSymbolAddress((void**)&pg_c1, g_c1);
    float* pg_decfea; cudaGetSymbolAddress((void**)&pg_decfea, g_decfea);
    float* pg_ct;     cudaGetSymbolAddress((void**)&pg_ct, g_ct);
    float* pg_out1;   cudaGetSymbolAddress((void**)&pg_out1, g_out1);

    // embedding gather
    k_emb<<<Bq, EMBq>>>(y, emb);
    // x = [ct1 | emb] @ Wx^T + bx   (K=512+128, N=128)
    gemm_seg<<<dim3(EMBq / 32, 2), 256>>>(ct1, NN, Wx, NN + EMBq,
                                          pg_emb, EMBq, Wx + NN, NN + EMBq,
                                          NN, EMBq, bx, pg_x, EMBq);
    // gates = x @ w_ih^T + h0 @ w_hh^T   (K=128+256, N=1024)
    gemm_seg<<<dim3(4 * Hh / 32, 2), 256>>>(pg_x, EMBq, w_ih, EMBq,
                                            s_h, Hh, w_hh, Hh,
                                            EMBq, Hh, (const float*)nullptr,
                                            pg_gates, 4 * Hh);
    k_lstm_elem<<<Bq, Hh>>>(s_c, b_ih, b_hh, out, osz);
    // dec_fea = [h1 | c1] @ Wp^T + bp   (K=256+256, N=512)
    gemm_seg<<<dim3(NN / 32, 2), 256>>>(pg_h1, Hh, Wp, NN,
                                        pg_c1, Hh, Wp + Hh, NN,
                                        Hh, Hh, bp, pg_decfea, NN);
    k_scores<<<(Bq * TKq) / 8, 256>>>(enc_feat, cov, Wc, v_w);
    k_attsoft<<<Bq, 512>>>(mask, cov, out, osz);
    k_ct<<<Bq, 512>>>(enc_out, out, osz);
    k_pgen<<<Bq, 128>>>(Wpg, bpg, out, osz);
    // out1 = [h1 | c_t] @ W1^T + b1   (K=256+512, N=256)
    gemm_seg<<<dim3(Hh / 32, 2), 256>>>(pg_h1, Hh, W1, Hh + NN,
                                        pg_ct, NN, W1 + Hh, Hh + NN,
                                        Hh, NN, b1, pg_out1, Hh);
    k_logits<<<(Vq + GN - 1) / GN, 256>>>(W2, b2);
    k_vstats<<<dim3(4, Bq), 256>>>();
    dim3 gf((VXq + 511) / 512, Bq);
    k_final<<<gf, 512>>>(out, osz);
    k_scatter<<<(Bq * TKq + 255) / 256, 256>>>(ebev, out, osz);
}

// round 5
// speedup vs baseline: 2.1834x; 1.2175x over previous
#include <cuda_runtime.h>
#include <math.h>
#include <stdint.h>

// ---------------- problem constants ----------------
#define Bq    128
#define Hh    256
#define NN    512     // 2H
#define TKq   400
#define EMBq  128
#define Vq    50000
#define OOVq  10
#define VXq   (Vq + OOVq)

#define F_INF __int_as_float(0x7f800000)

// output segment offsets (flattened tuple order)
#define OFF_FINAL 0LL
#define OFF_H    6401280LL                 // B*(V+OOV)
#define OFF_C    (OFF_H  + (long long)Bq*Hh)
#define OFF_CT   (OFF_C  + (long long)Bq*Hh)
#define OFF_ATTN (OFF_CT + (long long)Bq*NN)
#define OFF_PGEN (OFF_ATTN + (long long)Bq*TKq)
#define OFF_COV  (OFF_PGEN + Bq)

// ---------------- scratch (device globals, no allocation) ----------------
__device__ float g_emb[Bq * EMBq];
__device__ float g_x[Bq * EMBq];
__device__ float g_gates[Bq * 4 * Hh];
__device__ float g_h1[Bq * Hh];
__device__ float g_c1[Bq * Hh];
__device__ float g_decfea[Bq * NN];
__device__ float g_scores[Bq * TKq];
__device__ float g_attn[Bq * TKq];
__device__ float g_ct[Bq * NN];
__device__ float g_pgen[Bq];
__device__ float g_out1[Bq * Hh];
__device__ float g_logits[(size_t)Bq * Vq];
__device__ float g_pm[Bq * 4];
__device__ float g_ps[Bq * 4];

__device__ __forceinline__ float sigmoidf_(float x) {
    return 1.0f / (1.0f + __expf(-x));
}
__device__ __forceinline__ float tanh_fast(float x) {
    float y;
    asm("tanh.approx.f32 %0, %1;" : "=f"(y) : "f"(x));
    return y;
}
__device__ __forceinline__ uint32_t smem_u32(const void* p) {
    uint32_t a;
    asm("{ .reg .u64 t; cvta.to.shared.u64 t, %1; cvt.u32.u64 %0, t; }"
        : "=r"(a) : "l"(p));
    return a;
}

__device__ __forceinline__ float warpReduceSum(float v) {
    #pragma unroll
    for (int o = 16; o; o >>= 1) v += __shfl_xor_sync(0xffffffffu, v, o);
    return v;
}
__device__ __forceinline__ float warpReduceMax(float v) {
    #pragma unroll
    for (int o = 16; o; o >>= 1) v = fmaxf(v, __shfl_xor_sync(0xffffffffu, v, o));
    return v;
}
__device__ __forceinline__ float blockReduceSum(float v, float* red) {
    int w = threadIdx.x >> 5, l = threadIdx.x & 31;
    int nw = (blockDim.x + 31) >> 5;
    v = warpReduceSum(v);
    if (l == 0) red[w] = v;
    __syncthreads();
    float r = (threadIdx.x < nw) ? red[threadIdx.x] : 0.0f;
    if (w == 0) {
        r = warpReduceSum(r);
        if (l == 0) red[0] = r;
    }
    __syncthreads();
    r = red[0];
    __syncthreads();
    return r;
}
__device__ __forceinline__ float blockReduceMax(float v, float* red) {
    int w = threadIdx.x >> 5, l = threadIdx.x & 31;
    int nw = (blockDim.x + 31) >> 5;
    v = warpReduceMax(v);
    if (l == 0) red[w] = v;
    __syncthreads();
    float r = (threadIdx.x < nw) ? red[threadIdx.x] : -F_INF;
    if (w == 0) {
        r = warpReduceMax(r);
        if (l == 0) red[0] = r;
    }
    __syncthreads();
    r = red[0];
    __syncthreads();
    return r;
}

// ---------------- embedding gather ----------------
__global__ void k_emb(const int* __restrict__ y, const float* __restrict__ emb) {
    int b = blockIdx.x;
    g_emb[b * EMBq + threadIdx.x] = emb[(size_t)y[b] * EMBq + threadIdx.x];
}

// ---------------- generic 2-segment GEMM (small layers) ----------------
__global__ __launch_bounds__(256) void gemm_seg(
    const float* __restrict__ A1, int lda1, const float* __restrict__ Wg1, int ws1,
    const float* __restrict__ A2, int lda2, const float* __restrict__ Wg2, int ws2,
    int K1, int K2, const float* __restrict__ bias, float* __restrict__ C, int N) {
    __shared__ float As[32][65];
    __shared__ float Bs[32][33];
    int n0 = blockIdx.x * 32;
    int m0 = blockIdx.y * 64;
    int tid = threadIdx.x;
    int tidn = tid & 15;
    int tidm = tid >> 4;
    float acc[4][2];
    #pragma unroll
    for (int i = 0; i < 4; i++) { acc[i][0] = 0.f; acc[i][1] = 0.f; }

    int K = K1 + K2;
    for (int kk = 0; kk < K; kk += 32) {
        const float* Aseg; const float* Wseg; int lda, ws, ko;
        if (kk < K1) { Aseg = A1; Wseg = Wg1; lda = lda1; ws = ws1; ko = kk; }
        else         { Aseg = A2; Wseg = Wg2; lda = lda2; ws = ws2; ko = kk - K1; }
        #pragma unroll
        for (int it = 0; it < 2; it++) {
            int idx = tid + it * 256;
            int m = idx >> 3;
            int k4 = (idx & 7) * 4;
            float4 a = *(const float4*)(Aseg + (size_t)(m0 + m) * lda + ko + k4);
            As[k4 + 0][m] = a.x; As[k4 + 1][m] = a.y;
            As[k4 + 2][m] = a.z; As[k4 + 3][m] = a.w;
        }
        {
            int n = tid >> 3;
            int k4 = (tid & 7) * 4;
            float4 w = *(const float4*)(Wseg + (size_t)(n0 + n) * ws + ko + k4);
            Bs[k4 + 0][n] = w.x; Bs[k4 + 1][n] = w.y;
            Bs[k4 + 2][n] = w.z; Bs[k4 + 3][n] = w.w;
        }
        __syncthreads();
        #pragma unroll
        for (int k = 0; k < 32; k++) {
            float a[4], bb[2];
            #pragma unroll
            for (int i = 0; i < 4; i++) a[i] = As[k][tidm + 16 * i];
            bb[0] = Bs[k][tidn];
            bb[1] = Bs[k][tidn + 16];
            #pragma unroll
            for (int i = 0; i < 4; i++) {
                acc[i][0] = fmaf(a[i], bb[0], acc[i][0]);
                acc[i][1] = fmaf(a[i], bb[1], acc[i][1]);
            }
        }
        __syncthreads();
    }
    #pragma unroll
    for (int j = 0; j < 2; j++) {
        int n = n0 + tidn + 16 * j;
        float bv = bias ? bias[n] : 0.0f;
        #pragma unroll
        for (int i = 0; i < 4; i++) {
            int m = m0 + tidm + 16 * i;
            C[(size_t)m * N + n] = acc[i][j] + bv;
        }
    }
}

// ---------------- LSTM elementwise ----------------
__global__ void k_lstm_elem(const float* __restrict__ c0,
                            const float* __restrict__ b_ih, const float* __restrict__ b_hh,
                            float* __restrict__ out, long long out_size) {
    int b = blockIdx.x;
    int h = threadIdx.x; // 256
    const float* g = g_gates + (size_t)b * 4 * Hh;
    float gi = g[h]            + b_ih[h]            + b_hh[h];
    float gf = g[Hh + h]       + b_ih[Hh + h]       + b_hh[Hh + h];
    float gg = g[2 * Hh + h]   + b_ih[2 * Hh + h]   + b_hh[2 * Hh + h];
    float go = g[3 * Hh + h]   + b_ih[3 * Hh + h]   + b_hh[3 * Hh + h];
    float c1 = sigmoidf_(gf) * c0[b * Hh + h] + sigmoidf_(gi) * tanhf(gg);
    float h1 = sigmoidf_(go) * tanhf(c1);
    g_h1[b * Hh + h] = h1;
    g_c1[b * Hh + h] = c1;
    long long ih = OFF_H + b * Hh + h;
    long long ic = OFF_C + b * Hh + h;
    if (ih < out_size) out[ih] = h1;
    if (ic < out_size) out[ic] = c1;
}

// ---------------- attention scores (warp per (b,t)) ----------------
__global__ void k_scores(const float* __restrict__ encf, const float* __restrict__ cov,
                         const float* __restrict__ Wc, const float* __restrict__ vw) {
    int gw = (blockIdx.x * blockDim.x + threadIdx.x) >> 5;
    int lane = threadIdx.x & 31;
    if (gw >= Bq * TKq) return;
    int b = gw / TKq;
    float cv = cov[gw];
    const float4* ef = (const float4*)(encf + (size_t)gw * NN);
    const float4* df = (const float4*)(g_decfea + (size_t)b * NN);
    const float4* wc = (const float4*)Wc;
    const float4* vv = (const float4*)vw;
    float acc = 0.0f;
    #pragma unroll
    for (int i = lane; i < NN / 4; i += 32) {
        float4 a = ef[i], d = df[i], w = wc[i], v = vv[i];
        acc += tanh_fast(a.x + d.x + cv * w.x) * v.x;
        acc += tanh_fast(a.y + d.y + cv * w.y) * v.y;
        acc += tanh_fast(a.z + d.z + cv * w.z) * v.z;
        acc += tanh_fast(a.w + d.w + cv * w.w) * v.w;
    }
    acc = warpReduceSum(acc);
    if (lane == 0) g_scores[gw] = acc;
}

// ---------------- attention softmax + coverage ----------------
__global__ void k_attsoft(const float* __restrict__ mask, const float* __restrict__ cov,
                          float* __restrict__ out, long long out_size) {
    int b = blockIdx.x;
    int t = threadIdx.x; // 512 threads, TK=400 active
    __shared__ float red[32];
    float sc = (t < TKq) ? g_scores[b * TKq + t] : -F_INF;
    float mx = blockReduceMax(sc, red);
    float ex = 0.0f;
    if (t < TKq) ex = __expf(sc - mx) * mask[b * TKq + t];
    float sum = blockReduceSum(ex, red);
    if (t < TKq) {
        float a = ex / sum;
        g_attn[b * TKq + t] = a;
        long long ia = OFF_ATTN + b * TKq + t;
        if (ia < out_size) out[ia] = a;
        long long icov = OFF_COV + b * TKq + t;
        if (icov < out_size) out[icov] = cov[b * TKq + t] + a;
    }
}

// ---------------- c_t = attn @ encoder_outputs ----------------
__global__ void k_ct(const float* __restrict__ enc, float* __restrict__ out,
                     long long out_size) {
    int b = blockIdx.x;
    int n = threadIdx.x; // 512
    __shared__ float at[TKq];
    for (int j = threadIdx.x; j < TKq; j += blockDim.x) at[j] = g_attn[b * TKq + j];
    __syncthreads();
    const float* e = enc + (size_t)b * TKq * NN + n;
    float acc = 0.0f;
    #pragma unroll 4
    for (int t = 0; t < TKq; t++) acc = fmaf(at[t], e[(size_t)t * NN], acc);
    g_ct[b * NN + n] = acc;
    long long ic = OFF_CT + b * NN + n;
    if (ic < out_size) out[ic] = acc;
}

// ---------------- p_gen ----------------
__global__ void k_pgen(const float* __restrict__ Wpg, const float* __restrict__ bpg,
                       float* __restrict__ out, long long out_size) {
    int b = blockIdx.x;
    __shared__ float red[32];
    float acc = 0.0f;
    for (int j = threadIdx.x; j < 1152; j += blockDim.x) {
        float v;
        if (j < 512)       v = g_ct[b * NN + j];
        else if (j < 768)  v = g_h1[b * Hh + (j - 512)];
        else if (j < 1024) v = g_c1[b * Hh + (j - 768)];
        else               v = g_x[b * EMBq + (j - 1024)];
        acc = fmaf(v, Wpg[j], acc);
    }
    acc = blockReduceSum(acc, red);
    if (threadIdx.x == 0) {
        float p = sigmoidf_(acc + bpg[0]);
        g_pgen[b] = p;
        long long ip = OFF_PGEN + b;
        if (ip < out_size) out[ip] = p;
    }
}

// ================= tf32 mma.sync logits GEMM =================
// C[128, 50000] = out1[128,256] @ W2[50000,256]^T + b2
// Per CTA: 128(batch) x 128(vocab), K=256 in 8 chunks of 32,
// cp.async double-buffered SMEM, 8 warps each 64x32 via m16n8k8 tf32.
#define LSTRIDE 36
#define CHUNK_F (128 * LSTRIDE)

__device__ __forceinline__ void mma_tf32(float* c, const uint32_t* a, const uint32_t* b) {
    asm volatile(
        "mma.sync.aligned.m16n8k8.row.col.f32.tf32.tf32.f32 "
        "{%0,%1,%2,%3}, {%4,%5,%6,%7}, {%8,%9}, {%0,%1,%2,%3};"
        : "+f"(c[0]), "+f"(c[1]), "+f"(c[2]), "+f"(c[3])
        : "r"(a[0]), "r"(a[1]), "r"(a[2]), "r"(a[3]), "r"(b[0]), "r"(b[1]));
}

__global__ __launch_bounds__(256) void k_logits_mma(const float* __restrict__ W2,
                                                    const float* __restrict__ b2) {
    extern __shared__ float sm[];
    uint32_t smb = smem_u32(sm);
    int tid = threadIdx.x;
    int lane = tid & 31, wid = tid >> 5;
    int gid = lane >> 2, tig = lane & 3;
    int n0 = blockIdx.x * 128;
    int m0w = (wid >> 2) * 64;   // warp M offset (0/64)
    int n0w = (wid & 3) * 32;    // warp N offset within tile

    float acc[4][4][4];
    #pragma unroll
    for (int i = 0; i < 4; i++)
        #pragma unroll
        for (int j = 0; j < 4; j++)
            #pragma unroll
            for (int q = 0; q < 4; q++) acc[i][j][q] = 0.0f;

    // prefetch helper (macro-style to keep immediates)
    #define PREFETCH(kc, buf) do {                                              \
        uint32_t dA = smb + (uint32_t)(buf) * 2u * CHUNK_F * 4u;                 \
        uint32_t dB = dA + CHUNK_F * 4u;                                         \
        _Pragma("unroll")                                                        \
        for (int it = 0; it < 4; it++) {                                         \
            int flat = tid + it * 256;                                           \
            int row = flat >> 3, kq = flat & 7;                                  \
            const float* sa = g_out1 + (size_t)row * Hh + (kc) * 32 + kq * 4;    \
            asm volatile("cp.async.ca.shared.global [%0], [%1], 16;"             \
                :: "r"(dA + (uint32_t)(row * LSTRIDE + kq * 4) * 4u), "l"(sa));  \
            int n = n0 + row;                                                    \
            int nc = (n < Vq) ? n : (Vq - 1);                                    \
            int sz = (n < Vq) ? 16 : 0;                                          \
            const float* sb = W2 + (size_t)nc * Hh + (kc) * 32 + kq * 4;         \
            asm volatile("cp.async.ca.shared.global [%0], [%1], 16, %2;"         \
                :: "r"(dB + (uint32_t)(row * LSTRIDE + kq * 4) * 4u), "l"(sb),   \
                   "r"(sz));                                                     \
        }                                                                        \
        asm volatile("cp.async.commit_group;");                                  \
    } while (0)

    PREFETCH(0, 0);
    #pragma unroll 1
    for (int kc = 0; kc < 8; kc++) {
        if (kc < 7) {
            PREFETCH(kc + 1, (kc + 1) & 1);
            asm volatile("cp.async.wait_group 1;");
        } else {
            asm volatile("cp.async.wait_group 0;");
        }
        __syncthreads();
        const float* As = sm + (kc & 1) * 2 * CHUNK_F;
        const float* Bs = As + CHUNK_F;
        #pragma unroll
        for (int ks = 0; ks < 4; ks++) {
            int k0 = ks * 8;
            uint32_t a[4][4], b[4][2];
            #pragma unroll
            for (int i = 0; i < 4; i++) {
                int r = m0w + i * 16 + gid;
                a[i][0] = __float_as_uint(As[r * LSTRIDE + k0 + tig]);
                a[i][1] = __float_as_uint(As[(r + 8) * LSTRIDE + k0 + tig]);
                a[i][2] = __float_as_uint(As[r * LSTRIDE + k0 + tig + 4]);
                a[i][3] = __float_as_uint(As[(r + 8) * LSTRIDE + k0 + tig + 4]);
            }
            #pragma unroll
            for (int j = 0; j < 4; j++) {
                int n = n0w + j * 8 + gid;
                b[j][0] = __float_as_uint(Bs[n * LSTRIDE + k0 + tig]);
                b[j][1] = __float_as_uint(Bs[n * LSTRIDE + k0 + tig + 4]);
            }
            #pragma unroll
            for (int i = 0; i < 4; i++)
                #pragma unroll
                for (int j = 0; j < 4; j++) mma_tf32(acc[i][j], a[i], b[j]);
        }
        __syncthreads();
    }

    // epilogue: write logits + bias (float2, coalesced within groups)
    #pragma unroll
    for (int j = 0; j < 4; j++) {
        int col = n0 + n0w + j * 8 + tig * 2;
        if (col < Vq) {
            float bx0 = b2[col], bx1 = b2[col + 1];
            #pragma unroll
            for (int i = 0; i < 4; i++) {
                int r0 = m0w + i * 16 + gid;
                float2 v0 = make_float2(acc[i][j][0] + bx0, acc[i][j][1] + bx1);
                float2 v1 = make_float2(acc[i][j][2] + bx0, acc[i][j][3] + bx1);
                *(float2*)(g_logits + (size_t)r0 * Vq + col) = v0;
                *(float2*)(g_logits + (size_t)(r0 + 8) * Vq + col) = v1;
            }
        }
    }
    #undef PREFETCH
}

// ---------------- vocab softmax stats: online, 4-way split ----------------
__global__ void k_vstats() {
    int b = blockIdx.y;
    int chunk = blockIdx.x; // 0..3
    int v0 = chunk * (Vq / 4);
    int v1 = v0 + (Vq / 4);
    const float* row = g_logits + (size_t)b * Vq;
    float m = -F_INF, s = 0.0f;
    for (int v = v0 + threadIdx.x; v < v1; v += blockDim.x) {
        float x = row[v];
        if (x > m) { s *= __expf(m - x); m = x; }
        s += __expf(x - m);
    }
    #pragma unroll
    for (int o = 16; o; o >>= 1) {
        float m2 = __shfl_xor_sync(0xffffffffu, m, o);
        float s2 = __shfl_xor_sync(0xffffffffu, s, o);
        float mn = fmaxf(m, m2);
        s = s * __expf(m - mn) + s2 * __expf(m2 - mn);
        m = mn;
    }
    __shared__ float sm_[8], ss[8];
    int w = threadIdx.x >> 5, l = threadIdx.x & 31;
    if (l == 0) { sm_[w] = m; ss[w] = s; }
    __syncthreads();
    if (threadIdx.x == 0) {
        int nw = blockDim.x >> 5;
        float M = sm_[0], S = ss[0];
        for (int i = 1; i < nw; i++) {
            float mn = fmaxf(M, sm_[i]);
            S = S * __expf(M - mn) + ss[i] * __expf(sm_[i] - mn);
            M = mn;
        }
        g_pm[b * 4 + chunk] = M;
        g_ps[b * 4 + chunk] = S;
    }
}

// ---------------- final dist base ----------------
__global__ void k_final(float* __restrict__ out, long long out_size) {
    int v = blockIdx.x * blockDim.x + threadIdx.x;
    int b = blockIdx.y;
    if (v >= VXq) return;
    float M = g_pm[b * 4], S = g_ps[b * 4];
    #pragma unroll
    for (int i = 1; i < 4; i++) {
        float m2 = g_pm[b * 4 + i], s2 = g_ps[b * 4 + i];
        float mn = fmaxf(M, m2);
        S = S * __expf(M - mn) + s2 * __expf(m2 - mn);
        M = mn;
    }
    float val = 0.0f;
    if (v < Vq)
        val = g_pgen[b] * __expf(g_logits[(size_t)b * Vq + v] - M) / S;
    long long idx = OFF_FINAL + (long long)b * VXq + v;
    if (idx < out_size) out[idx] = val;
}

// ---------------- copy scatter-add ----------------
__global__ void k_scatter(const int* __restrict__ ebev, float* __restrict__ out,
                          long long out_size) {
    int i = blockIdx.x * blockDim.x + threadIdx.x;
    if (i >= Bq * TKq) return;
    int b = i / TKq;
    float add = (1.0f - g_pgen[b]) * g_attn[i];
    int tgt = ebev[i];
    long long idx = OFF_FINAL + (long long)b * VXq + tgt;
    if (idx < out_size && tgt >= 0 && tgt < VXq) atomicAdd(&out[idx], add);
}

// ---------------- launch ----------------
extern "C" void kernel_launch(void* const* d_in, const int* in_sizes, int n_in,
                              void* d_out, int out_size) {
    const int*   y        = (const int*)  d_in[0];
    const float* s_h      = (const float*)d_in[1];
    const float* s_c      = (const float*)d_in[2];
    const float* enc_out  = (const float*)d_in[3];
    const float* enc_feat = (const float*)d_in[4];
    const float* mask     = (const float*)d_in[5];
    const float* ct1      = (const float*)d_in[6];
    const int*   ebev     = (const int*)  d_in[8];
    const float* cov      = (const float*)d_in[9];
    const float* emb      = (const float*)d_in[11];
    const float* Wx       = (const float*)d_in[12];
    const float* bx       = (const float*)d_in[13];
    const float* w_ih     = (const float*)d_in[14];
    const float* b_ih     = (const float*)d_in[15];
    const float* w_hh     = (const float*)d_in[16];
    const float* b_hh     = (const float*)d_in[17];
    const float* Wp       = (const float*)d_in[18];
    const float* bp       = (const float*)d_in[19];
    const float* v_w      = (const float*)d_in[20];
    const float* Wc       = (const float*)d_in[21];
    const float* Wpg      = (const float*)d_in[22];
    const float* bpg      = (const float*)d_in[23];
    const float* W1       = (const float*)d_in[24];
    const float* b1       = (const float*)d_in[25];
    const float* W2       = (const float*)d_in[26];
    const float* b2       = (const float*)d_in[27];
    float* out = (float*)d_out;
    long long osz = (long long)out_size;

    float* pg_emb;    cudaGetSymbolAddress((void**)&pg_emb, g_emb);
    float* pg_x;      cudaGetSymbolAddress((void**)&pg_x, g_x);
    float* pg_gates;  cudaGetSymbolAddress((void**)&pg_gates, g_gates);
    float* pg_h1;     cudaGetSymbolAddress((void**)&pg_h1, g_h1);
    float* pg_c1;     cudaGetSymbolAddress((void**)&pg_c1, g_c1);
    float* pg_decfea; cudaGetSymbolAddress((void**)&pg_decfea, g_decfea);
    float* pg_ct;     cudaGetSymbolAddress((void**)&pg_ct, g_ct);
    float* pg_out1;   cudaGetSymbolAddress((void**)&pg_out1, g_out1);

    k_emb<<<Bq, EMBq>>>(y, emb);
    gemm_seg<<<dim3(EMBq / 32, 2), 256>>>(ct1, NN, Wx, NN + EMBq,
                                          pg_emb, EMBq, Wx + NN, NN + EMBq,
                                          NN, EMBq, bx, pg_x, EMBq);
    gemm_seg<<<dim3(4 * Hh / 32, 2), 256>>>(pg_x, EMBq, w_ih, EMBq,
                                            s_h, Hh, w_hh, Hh,
                                            EMBq, Hh, (const float*)nullptr,
                                            pg_gates, 4 * Hh);
    k_lstm_elem<<<Bq, Hh>>>(s_c, b_ih, b_hh, out, osz);
    gemm_seg<<<dim3(NN / 32, 2), 256>>>(pg_h1, Hh, Wp, NN,
                                        pg_c1, Hh, Wp + Hh, NN,
                                        Hh, Hh, bp, pg_decfea, NN);
    k_scores<<<(Bq * TKq) / 8, 256>>>(enc_feat, cov, Wc, v_w);
    k_attsoft<<<Bq, 512>>>(mask, cov, out, osz);
    k_ct<<<Bq, 512>>>(enc_out, out, osz);
    k_pgen<<<Bq, 128>>>(Wpg, bpg, out, osz);
    gemm_seg<<<dim3(Hh / 32, 2), 256>>>(pg_h1, Hh, W1, Hh + NN,
                                        pg_ct, NN, W1 + Hh, Hh + NN,
                                        Hh, NN, b1, pg_out1, Hh);

    cudaFuncSetAttribute(k_logits_mma, cudaFuncAttributeMaxDynamicSharedMemorySize,
                         4 * CHUNK_F * 4);
    k_logits_mma<<<(Vq + 127) / 128, 256, 4 * CHUNK_F * 4>>>(W2, b2);
    k_vstats<<<dim3(4, Bq), 256>>>();
    dim3 gf((VXq + 511) / 512, Bq);
    k_final<<<gf, 512>>>(out, osz);
    k_scatter<<<(Bq * TKq + 255) / 256, 256>>>(ebev, out, osz);
}

// round 7
// speedup vs baseline: 2.2000x; 1.0076x over previous
#include <cuda_runtime.h>
#include <math.h>
#include <stdint.h>

// ---------------- problem constants ----------------
#define Bq    128
#define Hh    256
#define NN    512     // 2H
#define TKq   400
#define EMBq  128
#define Vq    50000
#define OOVq  10
#define VXq   (Vq + OOVq)
#define NT    391     // ceil(Vq/128) vocab tiles

#define F_INF __int_as_float(0x7f800000)
#define NEG_BIG (-1.0e30f)

// output segment offsets (flattened tuple order)
#define OFF_FINAL 0LL
#define OFF_H    6401280LL                 // B*(V+OOV)
#define OFF_C    (OFF_H  + (long long)Bq*Hh)
#define OFF_CT   (OFF_C  + (long long)Bq*Hh)
#define OFF_ATTN (OFF_CT + (long long)Bq*NN)
#define OFF_PGEN (OFF_ATTN + (long long)Bq*TKq)
#define OFF_COV  (OFF_PGEN + Bq)

// ---------------- scratch (device globals, no allocation) ----------------
__device__ float g_x[Bq * EMBq];
__device__ float g_h1[Bq * Hh];
__device__ float g_c1[Bq * Hh];
__device__ float g_decfea[Bq * NN];
__device__ float g_attn[Bq * TKq];
__device__ float g_ct[Bq * NN];
__device__ float g_pgen[Bq];
__device__ float g_out1[Bq * Hh];
__device__ float g_logits[(size_t)Bq * Vq];
__device__ float g_pm[Bq * NT];
__device__ float g_ps[Bq * NT];
__device__ float g_rmax[Bq];
__device__ float g_rsum[Bq];

__device__ __forceinline__ float sigmoidf_(float x) {
    return 1.0f / (1.0f + __expf(-x));
}
__device__ __forceinline__ float tanh_fast(float x) {
    float y;
    asm("tanh.approx.f32 %0, %1;" : "=f"(y) : "f"(x));
    return y;
}
__device__ __forceinline__ uint32_t smem_u32(const void* p) {
    uint32_t a;
    asm("{ .reg .u64 t; cvta.to.shared.u64 t, %1; cvt.u32.u64 %0, t; }"
        : "=r"(a) : "l"(p));
    return a;
}

__device__ __forceinline__ float warpReduceSum(float v) {
    #pragma unroll
    for (int o = 16; o; o >>= 1) v += __shfl_xor_sync(0xffffffffu, v, o);
    return v;
}
__device__ __forceinline__ float warpReduceMax(float v) {
    #pragma unroll
    for (int o = 16; o; o >>= 1) v = fmaxf(v, __shfl_xor_sync(0xffffffffu, v, o));
    return v;
}
__device__ __forceinline__ float blockReduceSum(float v, float* red) {
    int w = threadIdx.x >> 5, l = threadIdx.x & 31;
    int nw = (blockDim.x + 31) >> 5;
    v = warpReduceSum(v);
    if (l == 0) red[w] = v;
    __syncthreads();
    float r = (threadIdx.x < nw) ? red[threadIdx.x] : 0.0f;
    if (w == 0) {
        r = warpReduceSum(r);
        if (l == 0) red[0] = r;
    }
    __syncthreads();
    r = red[0];
    __syncthreads();
    return r;
}
__device__ __forceinline__ float blockReduceMax(float v, float* red) {
    int w = threadIdx.x >> 5, l = threadIdx.x & 31;
    int nw = (blockDim.x + 31) >> 5;
    v = warpReduceMax(v);
    if (l == 0) red[w] = v;
    __syncthreads();
    float r = (threadIdx.x < nw) ? red[threadIdx.x] : -F_INF;
    if (w == 0) {
        r = warpReduceMax(r);
        if (l == 0) red[0] = r;
    }
    __syncthreads();
    r = red[0];
    __syncthreads();
    return r;
}

// ---------------- K1: x = [ct1 | emb[y]] @ Wx^T + bx  (emb gather fused) ----------------
__global__ __launch_bounds__(256) void k_xgemm(
    const int* __restrict__ y, const float* __restrict__ ct1,
    const float* __restrict__ emb, const float* __restrict__ Wx,
    const float* __restrict__ bx) {
    __shared__ float As[32][65];
    __shared__ float Bs[32][33];
    __shared__ int ys[64];
    int n0 = blockIdx.x * 32;
    int m0 = blockIdx.y * 64;
    int tid = threadIdx.x;
    int tidn = tid & 15;
    int tidm = tid >> 4;
    if (tid < 64) ys[tid] = y[m0 + tid];
    float acc[4][2];
    #pragma unroll
    for (int i = 0; i < 4; i++) { acc[i][0] = 0.f; acc[i][1] = 0.f; }
    __syncthreads();

    const int K = NN + EMBq; // 640
    for (int kk = 0; kk < K; kk += 32) {
        #pragma unroll
        for (int it = 0; it < 2; it++) {
            int idx = tid + it * 256;
            int m = idx >> 3;
            int k4 = (idx & 7) * 4;
            float4 a;
            if (kk < NN) a = *(const float4*)(ct1 + (size_t)(m0 + m) * NN + kk + k4);
            else         a = *(const float4*)(emb + (size_t)ys[m] * EMBq + (kk - NN) + k4);
            As[k4 + 0][m] = a.x; As[k4 + 1][m] = a.y;
            As[k4 + 2][m] = a.z; As[k4 + 3][m] = a.w;
        }
        {
            int n = tid >> 3;
            int k4 = (tid & 7) * 4;
            float4 w = *(const float4*)(Wx + (size_t)(n0 + n) * K + kk + k4);
            Bs[k4 + 0][n] = w.x; Bs[k4 + 1][n] = w.y;
            Bs[k4 + 2][n] = w.z; Bs[k4 + 3][n] = w.w;
        }
        __syncthreads();
        #pragma unroll
        for (int k = 0; k < 32; k++) {
            float a[4], bb[2];
            #pragma unroll
            for (int i = 0; i < 4; i++) a[i] = As[k][tidm + 16 * i];
            bb[0] = Bs[k][tidn];
            bb[1] = Bs[k][tidn + 16];
            #pragma unroll
            for (int i = 0; i < 4; i++) {
                acc[i][0] = fmaf(a[i], bb[0], acc[i][0]);
                acc[i][1] = fmaf(a[i], bb[1], acc[i][1]);
            }
        }
        __syncthreads();
    }
    #pragma unroll
    for (int j = 0; j < 2; j++) {
        int n = n0 + tidn + 16 * j;
        float bv = bx[n];
        #pragma unroll
        for (int i = 0; i < 4; i++) {
            int m = m0 + tidm + 16 * i;
            g_x[(size_t)m * EMBq + n] = acc[i][j] + bv;
        }
    }
}

// ---------------- K2: gates GEMM (4 gate tiles) + LSTM elementwise, fused ----------------
__global__ __launch_bounds__(256) void k_gates_lstm(
    const float* __restrict__ h0, const float* __restrict__ c0,
    const float* __restrict__ w_ih, const float* __restrict__ b_ih,
    const float* __restrict__ w_hh, const float* __restrict__ b_hh,
    float* __restrict__ out, long long out_size) {
    __shared__ float As[32][33];
    __shared__ float Bs[4][32][33];
    int h0t = blockIdx.x * 32;   // hidden tile
    int m0 = blockIdx.y * 32;    // batch tile
    int tid = threadIdx.x;
    int tidn = tid & 15;
    int tidm = tid >> 4;
    float acc[4][2][2];
    #pragma unroll
    for (int g = 0; g < 4; g++)
        #pragma unroll
        for (int i = 0; i < 2; i++) { acc[g][i][0] = 0.f; acc[g][i][1] = 0.f; }

    const int K = EMBq + Hh; // 384
    for (int kk = 0; kk < K; kk += 32) {
        {
            int m = tid >> 3;
            int k4 = (tid & 7) * 4;
            float4 a;
            if (kk < EMBq) a = *(const float4*)(g_x + (size_t)(m0 + m) * EMBq + kk + k4);
            else           a = *(const float4*)(h0 + (size_t)(m0 + m) * Hh + (kk - EMBq) + k4);
            As[k4 + 0][m] = a.x; As[k4 + 1][m] = a.y;
            As[k4 + 2][m] = a.z; As[k4 + 3][m] = a.w;
        }
        #pragma unroll
        for (int g = 0; g < 4; g++) {
            int n = tid >> 3;
            int k4 = (tid & 7) * 4;
            int row = g * Hh + h0t + n;
            float4 w;
            if (kk < EMBq) w = *(const float4*)(w_ih + (size_t)row * EMBq + kk + k4);
            else           w = *(const float4*)(w_hh + (size_t)row * Hh + (kk - EMBq) + k4);
            Bs[g][k4 + 0][n] = w.x; Bs[g][k4 + 1][n] = w.y;
            Bs[g][k4 + 2][n] = w.z; Bs[g][k4 + 3][n] = w.w;
        }
        __syncthreads();
        #pragma unroll
        for (int k = 0; k < 32; k++) {
            float a0 = As[k][tidm], a1 = As[k][tidm + 16];
            #pragma unroll
            for (int g = 0; g < 4; g++) {
                float b0 = Bs[g][k][tidn], b1 = Bs[g][k][tidn + 16];
                acc[g][0][0] = fmaf(a0, b0, acc[g][0][0]);
                acc[g][0][1] = fmaf(a0, b1, acc[g][0][1]);
                acc[g][1][0] = fmaf(a1, b0, acc[g][1][0]);
                acc[g][1][1] = fmaf(a1, b1, acc[g][1][1]);
            }
        }
        __syncthreads();
    }
    #pragma unroll
    for (int i = 0; i < 2; i++) {
        #pragma unroll
        for (int j = 0; j < 2; j++) {
            int m = m0 + tidm + 16 * i;
            int h = h0t + tidn + 16 * j;
            float gi = acc[0][i][j] + b_ih[h]            + b_hh[h];
            float gf = acc[1][i][j] + b_ih[Hh + h]       + b_hh[Hh + h];
            float gg = acc[2][i][j] + b_ih[2 * Hh + h]   + b_hh[2 * Hh + h];
            float go = acc[3][i][j] + b_ih[3 * Hh + h]   + b_hh[3 * Hh + h];
            float c1 = sigmoidf_(gf) * c0[(size_t)m * Hh + h] + sigmoidf_(gi) * tanhf(gg);
            float h1 = sigmoidf_(go) * tanhf(c1);
            g_h1[(size_t)m * Hh + h] = h1;
            g_c1[(size_t)m * Hh + h] = c1;
            long long ih = OFF_H + (long long)m * Hh + h;
            long long ic = OFF_C + (long long)m * Hh + h;
            if (ih < out_size) out[ih] = h1;
            if (ic < out_size) out[ic] = c1;
        }
    }
}

// ---------------- generic 2-segment GEMM (decfea, out1) ----------------
__global__ __launch_bounds__(256) void gemm_seg(
    const float* __restrict__ A1, int lda1, const float* __restrict__ Wg1, int ws1,
    const float* __restrict__ A2, int lda2, const float* __restrict__ Wg2, int ws2,
    int K1, int K2, const float* __restrict__ bias, float* __restrict__ C, int N) {
    __shared__ float As[32][65];
    __shared__ float Bs[32][33];
    int n0 = blockIdx.x * 32;
    int m0 = blockIdx.y * 64;
    int tid = threadIdx.x;
    int tidn = tid & 15;
    int tidm = tid >> 4;
    float acc[4][2];
    #pragma unroll
    for (int i = 0; i < 4; i++) { acc[i][0] = 0.f; acc[i][1] = 0.f; }

    int K = K1 + K2;
    for (int kk = 0; kk < K; kk += 32) {
        const float* Aseg; const float* Wseg; int lda, ws, ko;
        if (kk < K1) { Aseg = A1; Wseg = Wg1; lda = lda1; ws = ws1; ko = kk; }
        else         { Aseg = A2; Wseg = Wg2; lda = lda2; ws = ws2; ko = kk - K1; }
        #pragma unroll
        for (int it = 0; it < 2; it++) {
            int idx = tid + it * 256;
            int m = idx >> 3;
            int k4 = (idx & 7) * 4;
            float4 a = *(const float4*)(Aseg + (size_t)(m0 + m) * lda + ko + k4);
            As[k4 + 0][m] = a.x; As[k4 + 1][m] = a.y;
            As[k4 + 2][m] = a.z; As[k4 + 3][m] = a.w;
        }
        {
            int n = tid >> 3;
            int k4 = (tid & 7) * 4;
            float4 w = *(const float4*)(Wseg + (size_t)(n0 + n) * ws + ko + k4);
            Bs[k4 + 0][n] = w.x; Bs[k4 + 1][n] = w.y;
            Bs[k4 + 2][n] = w.z; Bs[k4 + 3][n] = w.w;
        }
        __syncthreads();
        #pragma unroll
        for (int k = 0; k < 32; k++) {
            float a[4], bb[2];
            #pragma unroll
            for (int i = 0; i < 4; i++) a[i] = As[k][tidm + 16 * i];
            bb[0] = Bs[k][tidn];
            bb[1] = Bs[k][tidn + 16];
            #pragma unroll
            for (int i = 0; i < 4; i++) {
                acc[i][0] = fmaf(a[i], bb[0], acc[i][0]);
                acc[i][1] = fmaf(a[i], bb[1], acc[i][1]);
            }
        }
        __syncthreads();
    }
    #pragma unroll
    for (int j = 0; j < 2; j++) {
        int n = n0 + tidn + 16 * j;
        float bv = bias ? bias[n] : 0.0f;
        #pragma unroll
        for (int i = 0; i < 4; i++) {
            int m = m0 + tidm + 16 * i;
            C[(size_t)m * N + n] = acc[i][j] + bv;
        }
    }
}

// ---------------- K4: fused attention (scores+softmax+cov+ct+pgen) ----------------
__global__ __launch_bounds__(512) void k_attn(
    const float* __restrict__ encf, const float* __restrict__ enc,
    const float* __restrict__ mask, const float* __restrict__ cov,
    const float* __restrict__ Wc, const float* __restrict__ vw,
    const float* __restrict__ Wpg, const float* __restrict__ bpg,
    float* __restrict__ out, long long out_size) {
    int b = blockIdx.x;
    int tid = threadIdx.x;
    int wid = tid >> 5, lane = tid & 31;
    __shared__ float dec[NN], vws[NN], wcs[NN];
    __shared__ float sc[TKq], at[TKq];
    __shared__ float red[32];

    if (tid < NN) {
        dec[tid] = g_decfea[(size_t)b * NN + tid];
        vws[tid] = vw[tid];
        wcs[tid] = Wc[tid];
    }
    __syncthreads();

    // phase 1: scores
    const float4* dec4 = (const float4*)dec;
    const float4* vw4  = (const float4*)vws;
    const float4* wc4  = (const float4*)wcs;
    for (int t = wid; t < TKq; t += 16) {
        float cv = __ldg(cov + (size_t)b * TKq + t);
        const float4* ef = (const float4*)(encf + ((size_t)b * TKq + t) * NN);
        float acc = 0.0f;
        #pragma unroll
        for (int r = 0; r < 4; r++) {
            int i = lane + 32 * r;
            float4 a = ef[i], d = dec4[i], w = wc4[i], v = vw4[i];
            acc += tanh_fast(a.x + d.x + cv * w.x) * v.x;
            acc += tanh_fast(a.y + d.y + cv * w.y) * v.y;
            acc += tanh_fast(a.z + d.z + cv * w.z) * v.z;
            acc += tanh_fast(a.w + d.w + cv * w.w) * v.w;
        }
        acc = warpReduceSum(acc);
        if (lane == 0) sc[t] = acc;
    }
    __syncthreads();

    // phase 2: softmax + mask renorm + coverage out
    {
        float v = (tid < TKq) ? sc[tid] : -F_INF;
        float mx = blockReduceMax(v, red);
        float ex = 0.0f;
        if (tid < TKq) ex = __expf(v - mx) * mask[(size_t)b * TKq + tid];
        float sum = blockReduceSum(ex, red);
        if (tid < TKq) {
            float a = ex / sum;
            at[tid] = a;
            g_attn[(size_t)b * TKq + tid] = a;
            long long ia = OFF_ATTN + (long long)b * TKq + tid;
            if (ia < out_size) out[ia] = a;
            long long icov = OFF_COV + (long long)b * TKq + tid;
            if (icov < out_size) out[icov] = cov[(size_t)b * TKq + tid] + a;
        }
    }
    __syncthreads();

    // phase 3: c_t (thread tid handles feature tid)
    {
        const float* e = enc + (size_t)b * TKq * NN + tid;
        float acc = 0.0f;
        #pragma unroll 4
        for (int t = 0; t < TKq; t++) acc = fmaf(at[t], e[(size_t)t * NN], acc);
        g_ct[(size_t)b * NN + tid] = acc;
        long long ic = OFF_CT + (long long)b * NN + tid;
        if (ic < out_size) out[ic] = acc;
        vws[tid] = acc;  // stash c_t for p_gen dot (vw no longer needed)
    }
    __syncthreads();

    // phase 4: p_gen = sigmoid([ct, h1, c1, x] . Wpg + bpg)
    {
        float acc = 0.0f;
        for (int j = tid; j < 1152; j += 512) {
            float v;
            if (j < 512)       v = vws[j];
            else if (j < 768)  v = g_h1[(size_t)b * Hh + (j - 512)];
            else if (j < 1024) v = g_c1[(size_t)b * Hh + (j - 768)];
            else               v = g_x[(size_t)b * EMBq + (j - 1024)];
            acc = fmaf(v, Wpg[j], acc);
        }
        acc = blockReduceSum(acc, red);
        if (tid == 0) {
            float p = sigmoidf_(acc + bpg[0]);
            g_pgen[b] = p;
            long long ip = OFF_PGEN + b;
            if (ip < out_size) out[ip] = p;
        }
    }
}

// ================= tf32 mma.sync logits GEMM + stats partials =================
#define LSTRIDE 36
#define CHUNK_F (128 * LSTRIDE)

__device__ __forceinline__ void mma_tf32(float* c, const uint32_t* a, const uint32_t* b) {
    asm volatile(
        "mma.sync.aligned.m16n8k8.row.col.f32.tf32.tf32.f32 "
        "{%0,%1,%2,%3}, {%4,%5,%6,%7}, {%8,%9}, {%0,%1,%2,%3};"
        : "+f"(c[0]), "+f"(c[1]), "+f"(c[2]), "+f"(c[3])
        : "r"(a[0]), "r"(a[1]), "r"(a[2]), "r"(a[3]), "r"(b[0]), "r"(b[1]));
}

__global__ __launch_bounds__(256) void k_logits_mma(const float* __restrict__ W2,
                                                    const float* __restrict__ b2) {
    extern __shared__ float sm[];
    __shared__ float st_m[128][4];
    __shared__ float st_s[128][4];
    uint32_t smb = smem_u32(sm);
    int tid = threadIdx.x;
    int lane = tid & 31, wid = tid >> 5;
    int gid = lane >> 2, tig = lane & 3;
    int n0 = blockIdx.x * 128;
    int m0w = (wid >> 2) * 64;   // warp M offset (0/64)
    int n0w = (wid & 3) * 32;    // warp N offset within tile

    float acc[4][4][4];
    #pragma unroll
    for (int i = 0; i < 4; i++)
        #pragma unroll
        for (int j = 0; j < 4; j++)
            #pragma unroll
            for (int q = 0; q < 4; q++) acc[i][j][q] = 0.0f;

    #define PREFETCH(kc, buf) do {                                              \
        uint32_t dA = smb + (uint32_t)(buf) * 2u * CHUNK_F * 4u;                 \
        uint32_t dB = dA + CHUNK_F * 4u;                                         \
        _Pragma("unroll")                                                        \
        for (int it = 0; it < 4; it++) {                                         \
            int flat = tid + it * 256;                                           \
            int row = flat >> 3, kq = flat & 7;                                  \
            const float* sa = g_out1 + (size_t)row * Hh + (kc) * 32 + kq * 4;    \
            asm volatile("cp.async.ca.shared.global [%0], [%1], 16;"             \
                :: "r"(dA + (uint32_t)(row * LSTRIDE + kq * 4) * 4u), "l"(sa));  \
            int n = n0 + row;                                                    \
            int nc = (n < Vq) ? n : (Vq - 1);                                    \
            int sz = (n < Vq) ? 16 : 0;                                          \
            const float* sb = W2 + (size_t)nc * Hh + (kc) * 32 + kq * 4;         \
            asm volatile("cp.async.ca.shared.global [%0], [%1], 16, %2;"         \
                :: "r"(dB + (uint32_t)(row * LSTRIDE + kq * 4) * 4u), "l"(sb),   \
                   "r"(sz));                                                     \
        }                                                                        \
        asm volatile("cp.async.commit_group;");                                  \
    } while (0)

    PREFETCH(0, 0);
    #pragma unroll 1
    for (int kc = 0; kc < 8; kc++) {
        if (kc < 7) {
            PREFETCH(kc + 1, (kc + 1) & 1);
            asm volatile("cp.async.wait_group 1;");
        } else {
            asm volatile("cp.async.wait_group 0;");
        }
        __syncthreads();
        const float* As = sm + (kc & 1) * 2 * CHUNK_F;
        const float* Bs = As + CHUNK_F;
        #pragma unroll
        for (int ks = 0; ks < 4; ks++) {
            int k0 = ks * 8;
            uint32_t a[4][4], b[4][2];
            #pragma unroll
            for (int i = 0; i < 4; i++) {
                int r = m0w + i * 16 + gid;
                a[i][0] = __float_as_uint(As[r * LSTRIDE + k0 + tig]);
                a[i][1] = __float_as_uint(As[(r + 8) * LSTRIDE + k0 + tig]);
                a[i][2] = __float_as_uint(As[r * LSTRIDE + k0 + tig + 4]);
                a[i][3] = __float_as_uint(As[(r + 8) * LSTRIDE + k0 + tig + 4]);
            }
            #pragma unroll
            for (int j = 0; j < 4; j++) {
                int n = n0w + j * 8 + gid;
                b[j][0] = __float_as_uint(Bs[n * LSTRIDE + k0 + tig]);
                b[j][1] = __float_as_uint(Bs[n * LSTRIDE + k0 + tig + 4]);
            }
            #pragma unroll
            for (int i = 0; i < 4; i++)
                #pragma unroll
                for (int j = 0; j < 4; j++) mma_tf32(acc[i][j], a[i], b[j]);
        }
        __syncthreads();
    }
    #undef PREFETCH

    // epilogue: add bias, write logits, build per-(row, tile) max/sumexp partials.
    // NEG_BIG (finite) sentinel avoids -inf-(-inf)=NaN in empty-partition merges.
    float rm[4][2], rs[4][2];
    #pragma unroll
    for (int i = 0; i < 4; i++) { rm[i][0] = rm[i][1] = NEG_BIG; rs[i][0] = rs[i][1] = 0.f; }

    #pragma unroll
    for (int j = 0; j < 4; j++) {
        int col = n0 + n0w + j * 8 + tig * 2;
        bool valid = (col < Vq);
        float bx0 = 0.f, bx1 = 0.f;
        if (valid) { bx0 = b2[col]; bx1 = b2[col + 1]; }
        #pragma unroll
        for (int i = 0; i < 4; i++) {
            float v0 = acc[i][j][0] + bx0, v1 = acc[i][j][1] + bx1;
            float v2 = acc[i][j][2] + bx0, v3 = acc[i][j][3] + bx1;
            if (valid) {
                int r0 = m0w + i * 16 + gid;
                *(float2*)(g_logits + (size_t)r0 * Vq + col) = make_float2(v0, v1);
                *(float2*)(g_logits + (size_t)(r0 + 8) * Vq + col) = make_float2(v2, v3);
                float mp = fmaxf(v0, v1);
                float sp = __expf(v0 - mp) + __expf(v1 - mp);
                float mn = fmaxf(rm[i][0], mp);
                rs[i][0] = rs[i][0] * __expf(rm[i][0] - mn) + sp * __expf(mp - mn);
                rm[i][0] = mn;
                mp = fmaxf(v2, v3);
                sp = __expf(v2 - mp) + __expf(v3 - mp);
                mn = fmaxf(rm[i][1], mp);
                rs[i][1] = rs[i][1] * __expf(rm[i][1] - mn) + sp * __expf(mp - mn);
                rm[i][1] = mn;
            }
        }
    }
    // reduce across tig (quad) via shfl — finite sentinel keeps exp() well-defined
    #pragma unroll
    for (int i = 0; i < 4; i++) {
        #pragma unroll
        for (int hf = 0; hf < 2; hf++) {
            float m = rm[i][hf], s = rs[i][hf];
            #pragma unroll
            for (int o = 1; o <= 2; o <<= 1) {
                float m2 = __shfl_xor_sync(0xffffffffu, m, o);
                float s2 = __shfl_xor_sync(0xffffffffu, s, o);
                float mn = fmaxf(m, m2);
                s = s * __expf(m - mn) + s2 * __expf(m2 - mn);
                m = mn;
            }
            rm[i][hf] = m; rs[i][hf] = s;
        }
    }
    int wn = wid & 3;
    if (tig == 0) {
        #pragma unroll
        for (int i = 0; i < 4; i++) {
            #pragma unroll
            for (int hf = 0; hf < 2; hf++) {
                int row = m0w + i * 16 + gid + hf * 8;
                st_m[row][wn] = rm[i][hf];
                st_s[row][wn] = rs[i][hf];
            }
        }
    }
    __syncthreads();
    if (tid < 128) {
        float M = st_m[tid][0], S = st_s[tid][0];
        #pragma unroll
        for (int i = 1; i < 4; i++) {
            float m2 = st_m[tid][i], s2 = st_s[tid][i];
            float mn = fmaxf(M, m2);
            S = S * __expf(M - mn) + s2 * __expf(m2 - mn);
            M = mn;
        }
        g_pm[(size_t)tid * NT + blockIdx.x] = M;
        g_ps[(size_t)tid * NT + blockIdx.x] = S;
    }
}

// ---------------- merge per-tile stats -> per-row (M, S) ----------------
__global__ void k_vmerge() {
    int b = blockIdx.x;
    int tid = threadIdx.x; // 128
    float m = NEG_BIG, s = 0.0f;
    for (int t = tid; t < NT; t += 128) {
        float m2 = g_pm[(size_t)b * NT + t], s2 = g_ps[(size_t)b * NT + t];
        float mn = fmaxf(m, m2);
        s = s * __expf(m - mn) + s2 * __expf(m2 - mn);
        m = mn;
    }
    #pragma unroll
    for (int o = 16; o; o >>= 1) {
        float m2 = __shfl_xor_sync(0xffffffffu, m, o);
        float s2 = __shfl_xor_sync(0xffffffffu, s, o);
        float mn = fmaxf(m, m2);
        s = s * __expf(m - mn) + s2 * __expf(m2 - mn);
        m = mn;
    }
    __shared__ float sm_[4], ss_[4];
    int w = tid >> 5, l = tid & 31;
    if (l == 0) { sm_[w] = m; ss_[w] = s; }
    __syncthreads();
    if (tid == 0) {
        float M = sm_[0], S = ss_[0];
        #pragma unroll
        for (int i = 1; i < 4; i++) {
            float mn = fmaxf(M, sm_[i]);
            S = S * __expf(M - mn) + ss_[i] * __expf(sm_[i] - mn);
            M = mn;
        }
        g_rmax[b] = M;
        g_rsum[b] = S;
    }
}

// ---------------- final dist base ----------------
__global__ void k_final(float* __restrict__ out, long long out_size) {
    int v = blockIdx.x * blockDim.x + threadIdx.x;
    int b = blockIdx.y;
    if (v >= VXq) return;
    float val = 0.0f;
    if (v < Vq)
        val = g_pgen[b] * __expf(g_logits[(size_t)b * Vq + v] - g_rmax[b]) / g_rsum[b];
    long long idx = OFF_FINAL + (long long)b * VXq + v;
    if (idx < out_size) out[idx] = val;
}

// ---------------- copy scatter-add ----------------
__global__ void k_scatter(const int* __restrict__ ebev, float* __restrict__ out,
                          long long out_size) {
    int i = blockIdx.x * blockDim.x + threadIdx.x;
    if (i >= Bq * TKq) return;
    int b = i / TKq;
    float add = (1.0f - g_pgen[b]) * g_attn[i];
    int tgt = ebev[i];
    long long idx = OFF_FINAL + (long long)b * VXq + tgt;
    if (idx < out_size && tgt >= 0 && tgt < VXq) atomicAdd(&out[idx], add);
}

// ---------------- launch ----------------
extern "C" void kernel_launch(void* const* d_in, const int* in_sizes, int n_in,
                              void* d_out, int out_size) {
    const int*   y        = (const int*)  d_in[0];
    const float* s_h      = (const float*)d_in[1];
    const float* s_c      = (const float*)d_in[2];
    const float* enc_out  = (const float*)d_in[3];
    const float* enc_feat = (const float*)d_in[4];
    const float* mask     = (const float*)d_in[5];
    const float* ct1      = (const float*)d_in[6];
    const int*   ebev     = (const int*)  d_in[8];
    const float* cov      = (const float*)d_in[9];
    const float* emb      = (const float*)d_in[11];
    const float* Wx       = (const float*)d_in[12];
    const float* bx       = (const float*)d_in[13];
    const float* w_ih     = (const float*)d_in[14];
    const float* b_ih     = (const float*)d_in[15];
    const float* w_hh     = (const float*)d_in[16];
    const float* b_hh     = (const float*)d_in[17];
    const float* Wp       = (const float*)d_in[18];
    const float* bp       = (const float*)d_in[19];
    const float* v_w      = (const float*)d_in[20];
    const float* Wc       = (const float*)d_in[21];
    const float* Wpg      = (const float*)d_in[22];
    const float* bpg      = (const float*)d_in[23];
    const float* W1       = (const float*)d_in[24];
    const float* b1       = (const float*)d_in[25];
    const float* W2       = (const float*)d_in[26];
    const float* b2       = (const float*)d_in[27];
    float* out = (float*)d_out;
    long long osz = (long long)out_size;

    float* pg_h1;     cudaGetSymbolAddress((void**)&pg_h1, g_h1);
    float* pg_c1;     cudaGetSymbolAddress((void**)&pg_c1, g_c1);
    float* pg_decfea; cudaGetSymbolAddress((void**)&pg_decfea, g_decfea);
    float* pg_ct;     cudaGetSymbolAddress((void**)&pg_ct, g_ct);
    float* pg_out1;   cudaGetSymbolAddress((void**)&pg_out1, g_out1);

    // 1. x = [ct1 | emb[y]] @ Wx^T + bx
    k_xgemm<<<dim3(EMBq / 32, 2), 256>>>(y, ct1, emb, Wx, bx);
    // 2. gates GEMM + LSTM
    k_gates_lstm<<<dim3(Hh / 32, 4), 256>>>(s_h, s_c, w_ih, b_ih, w_hh, b_hh, out, osz);
    // 3. dec_fea = [h1 | c1] @ Wp^T + bp
    gemm_seg<<<dim3(NN / 32, 2), 256>>>(pg_h1, Hh, Wp, NN,
                                        pg_c1, Hh, Wp + Hh, NN,
                                        Hh, Hh, bp, pg_decfea, NN);
    // 4. fused attention (profiled slot)
    k_attn<<<Bq, 512>>>(enc_feat, enc_out, mask, cov, Wc, v_w, Wpg, bpg, out, osz);
    // 5. out1 = [h1 | c_t] @ W1^T + b1
    gemm_seg<<<dim3(Hh / 32, 2), 256>>>(pg_h1, Hh, W1, Hh + NN,
                                        pg_ct, NN, W1 + Hh, Hh + NN,
                                        Hh, NN, b1, pg_out1, Hh);
    // 6. logits GEMM + stats partials
    cudaFuncSetAttribute(k_logits_mma, cudaFuncAttributeMaxDynamicSharedMemorySize,
                         4 * CHUNK_F * 4);
    k_logits_mma<<<NT, 256, 4 * CHUNK_F * 4>>>(W2, b2);
    // 7. merge stats
    k_vmerge<<<Bq, 128>>>();
    // 8. final base dist
    dim3 gf((VXq + 511) / 512, Bq);
    k_final<<<gf, 512>>>(out, osz);
    // 9. copy scatter
    k_scatter<<<(Bq * TKq + 255) / 256, 256>>>(ebev, out, osz);
}